// round 2
// baseline (speedup 1.0000x reference)
#include <cuda_runtime.h>

#define BATCH 16
#define D 128
#define NN 16
#define E 120
#define OUTB (256 * 256)

// Scratch (no allocations allowed -> __device__ globals)
__device__ float g_tmp[BATCH][2][D][NN];   // l1@Ft, l2@Ft per batch
__device__ float g_P[BATCH][2][NN * NN];   // P1, P2 = Fs^T l Ft
__device__ float g_Mp[BATCH][NN * NN];     // node affinity Us^T Ut
__device__ int   g_both[BATCH][E];         // edge present in both graphs

// ---------------------------------------------------------------------------
// K1: tmp[b][m][d][j] = sum_d' relu(lam_m + lam_m^T)[d][d'] * Ft[b][d'][j]
// grid: 16 batches x 8 chunks of 16 d-rows, 256 threads
// ---------------------------------------------------------------------------
__global__ void k1_tmp(const float* __restrict__ Ft,
                       const float* __restrict__ lam1,
                       const float* __restrict__ lam2) {
    __shared__ float Fts[D * NN];     // [d'][j]
    __shared__ float w1s[16][D];
    __shared__ float w2s[16][D];

    const int b  = blockIdx.x >> 3;
    const int c0 = (blockIdx.x & 7) * 16;
    const int t  = threadIdx.x;

    const float* ft = Ft + b * D * NN;
    for (int idx = t; idx < D * NN; idx += 256) Fts[idx] = ft[idx];

    for (int idx = t; idx < 16 * D; idx += 256) {
        const int d  = idx >> 7;
        const int dp = idx & 127;
        const int dr = c0 + d;
        float v1 = lam1[dr * D + dp] + lam1[dp * D + dr];
        float v2 = lam2[dr * D + dp] + lam2[dp * D + dr];
        w1s[d][dp] = v1 > 0.f ? v1 : 0.f;
        w2s[d][dp] = v2 > 0.f ? v2 : 0.f;
    }
    __syncthreads();

    const int j    = t & 15;
    const int dloc = t >> 4;
    const float4* w1v = reinterpret_cast<const float4*>(w1s[dloc]);
    const float4* w2v = reinterpret_cast<const float4*>(w2s[dloc]);

    float a1 = 0.f, a2 = 0.f;
#pragma unroll
    for (int q = 0; q < D / 4; q++) {
        const float4 wa = w1v[q];
        const float4 wb = w2v[q];
        const float f0 = Fts[(4 * q + 0) * NN + j];
        const float f1 = Fts[(4 * q + 1) * NN + j];
        const float f2 = Fts[(4 * q + 2) * NN + j];
        const float f3 = Fts[(4 * q + 3) * NN + j];
        a1 += wa.x * f0 + wa.y * f1 + wa.z * f2 + wa.w * f3;
        a2 += wb.x * f0 + wb.y * f1 + wb.z * f2 + wb.w * f3;
    }
    g_tmp[b][0][c0 + dloc][j] = a1;
    g_tmp[b][1][c0 + dloc][j] = a2;
}

// ---------------------------------------------------------------------------
// K2: P1/P2[b][i][j] = sum_d Fs[b][d][i] * tmp[b][m][d][j]
//     Mp[b][i][j]    = sum_d Us[b][d][i] * Ut[b][d][j]
//     both[b][e]     = (A_src>0) & (A_tgt>0)
// grid: 16 blocks (one per batch), 256 threads
// ---------------------------------------------------------------------------
__global__ void k2_small(const float* __restrict__ Fs,
                         const float* __restrict__ Us,
                         const float* __restrict__ Ut,
                         const int* __restrict__ As,
                         const int* __restrict__ At) {
    __shared__ float Fss[D * NN];
    __shared__ float t1s[D * NN];
    __shared__ float t2s[D * NN];

    const int b = blockIdx.x;
    const int t = threadIdx.x;

    const float* fs  = Fs + b * D * NN;
    const float* tp1 = &g_tmp[b][0][0][0];
    const float* tp2 = &g_tmp[b][1][0][0];
    for (int idx = t; idx < D * NN; idx += 256) {
        Fss[idx] = fs[idx];
        t1s[idx] = tp1[idx];
        t2s[idx] = tp2[idx];
    }
    __syncthreads();

    const int i = t >> 4;
    const int j = t & 15;

    float p1 = 0.f, p2 = 0.f;
#pragma unroll
    for (int d = 0; d < D; d++) {
        const float f = Fss[d * NN + i];
        p1 += f * t1s[d * NN + j];
        p2 += f * t2s[d * NN + j];
    }
    g_P[b][0][t] = p1;
    g_P[b][1][t] = p2;

    float mp = 0.f;
#pragma unroll
    for (int d = 0; d < NN; d++)
        mp += Us[b * 256 + d * 16 + i] * Ut[b * 256 + d * 16 + j];
    g_Mp[b][t] = mp;

    if (t < E)
        g_both[b][t] = (As[b * E + t] > 0) && (At[b * E + t] > 0);
}

// ---------------------------------------------------------------------------
// K3: write M[b][p][q], p=i2p*16+i1p, q=i2q*16+i1q
//   M = (p==q ? Mp[p] : 0)
//     + [i2p<i2q][i1p<i1q] both[e2] both[e1]
//       * (P1[i2p,i1p] + P2[i2p,i1q] + P2[i2q,i1p] + P1[i2q,i1q])
//   e(a,b) = a*(29-a)/2 + b - 1  (strict upper triangle, row-major, n=16)
// grid: 256 blocks (b*16 + i2p), 256 threads (q)
// ---------------------------------------------------------------------------
__global__ void k3_write(float* __restrict__ out) {
    __shared__ float P1s[256];
    __shared__ float P2s[256];
    __shared__ float Mps[256];
    __shared__ int   boths[E];

    const int b   = blockIdx.x >> 4;
    const int i2p = blockIdx.x & 15;
    const int t   = threadIdx.x;

    P1s[t] = g_P[b][0][t];
    P2s[t] = g_P[b][1][t];
    Mps[t] = g_Mp[b][t];
    if (t < E) boths[t] = g_both[b][t];
    __syncthreads();

    const int i2q = t >> 4;
    const int i1q = t & 15;

    int e2ok = 0;
    if (i2p < i2q) {
        const int e2 = i2p * (29 - i2p) / 2 + i2q - 1;
        e2ok = boths[e2];
    }

    const float c_p2a = P2s[i2p * 16 + i1q];   // fixed per thread
    const float* p1_row_p = &P1s[i2p * 16];
    const float* p2_col_q = &P2s[i2q * 16];
    const float c_p1b = P1s[i2q * 16 + i1q];

    float* outb = out + b * OUTB + (i2p * 16) * 256 + t;

#pragma unroll
    for (int i1p = 0; i1p < 16; i1p++) {
        const int p = i2p * 16 + i1p;
        float v = (p == t) ? Mps[p] : 0.f;
        if (e2ok && i1p < i1q) {
            const int e1 = i1p * (29 - i1p) / 2 + i1q - 1;
            if (boths[e1])
                v += p1_row_p[i1p] + c_p2a + p2_col_q[i1p] + c_p1b;
        }
        outb[i1p * 256] = v;
    }
}

extern "C" void kernel_launch(void* const* d_in, const int* in_sizes, int n_in,
                              void* d_out, int out_size) {
    const int*   As   = (const int*)d_in[0];
    const int*   At   = (const int*)d_in[1];
    const float* Fs   = (const float*)d_in[2];
    const float* Ft   = (const float*)d_in[3];
    const float* Us   = (const float*)d_in[4];
    const float* Ut   = (const float*)d_in[5];
    const float* lam1 = (const float*)d_in[6];
    const float* lam2 = (const float*)d_in[7];
    float* out = (float*)d_out;

    k1_tmp<<<128, 256>>>(Ft, lam1, lam2);
    k2_small<<<16, 256>>>(Fs, Us, Ut, As, At);
    k3_write<<<256, 256>>>(out);
}

// round 4
// speedup vs baseline: 1.5456x; 1.5456x over previous
#include <cuda_runtime.h>

#define BATCH 16
#define D 128
#define NN 16
#define E 120
#define OUTB (256 * 256)

// Scratch (no allocations allowed -> __device__ globals)
__device__ float g_W[2][D * D];            // relu(lam_m + lam_m^T)
__device__ float g_tmp[BATCH][2][D][NN];   // W_m @ Ft per batch
__device__ float g_P[BATCH][2][NN * NN];   // P1, P2 = Fs^T W Ft
__device__ float g_Mp[BATCH][NN * NN];     // node affinity Us^T Ut
__device__ int   g_both[BATCH][E];         // edge present in both graphs

// ---------------------------------------------------------------------------
// kW: W_m[r][c] = relu(lam_m[r][c] + lam_m[c][r]), fully coalesced via 32x32
// smem tiles. grid: 32 blocks (m*16 + tile), 256 threads (8 rows x 32 cols).
// ---------------------------------------------------------------------------
__global__ void kW(const float* __restrict__ lam1,
                   const float* __restrict__ lam2) {
    __shared__ float As[32][32];
    __shared__ float Bs[32][33];   // padded: conflict-free column reads

    const int m    = blockIdx.x >> 4;
    const int tile = blockIdx.x & 15;
    const int r0   = (tile >> 2) * 32;
    const int c0   = (tile & 3) * 32;

    const float* lam = m ? lam2 : lam1;
    float*       W   = g_W[m];

    const int tx = threadIdx.x & 31;
    const int ty = threadIdx.x >> 5;   // 0..7

#pragma unroll
    for (int k = 0; k < 4; k++) {
        const int i = ty + 8 * k;
        As[i][tx] = lam[(r0 + i) * D + c0 + tx];   // direct tile
        Bs[i][tx] = lam[(c0 + i) * D + r0 + tx];   // transposed-source tile
    }
    __syncthreads();

#pragma unroll
    for (int k = 0; k < 4; k++) {
        const int i = ty + 8 * k;
        const float v = As[i][tx] + Bs[tx][i];     // lam[r][c] + lam[c][r]
        W[(r0 + i) * D + c0 + tx] = v > 0.f ? v : 0.f;
    }
}

// ---------------------------------------------------------------------------
// k1: tmp[b][m][d][j] = sum_d' W_m[d][d'] * Ft[b][d'][j]
// grid: 256 blocks = b*16 + m*8 + chunk (16 d-rows each), 256 threads
// ---------------------------------------------------------------------------
__global__ void k1_tmp(const float* __restrict__ Ft) {
    __shared__ float Fts[D * NN];     // [d'][j]
    __shared__ float ws[16][132];     // padded rows: no float4 bank conflict

    const int b  = blockIdx.x >> 4;
    const int m  = (blockIdx.x >> 3) & 1;
    const int c0 = (blockIdx.x & 7) * 16;
    const int t  = threadIdx.x;

    const float* ft = Ft + b * D * NN;
    for (int idx = t; idx < D * NN; idx += 256) Fts[idx] = ft[idx];

    const float* Wm = g_W[m];
    for (int idx = t; idx < 16 * D; idx += 256) {
        const int d  = idx >> 7;
        const int dp = idx & 127;
        ws[d][dp] = Wm[(c0 + d) * D + dp];         // coalesced
    }
    __syncthreads();

    const int j    = t & 15;
    const int dloc = t >> 4;
    const float4* wv = reinterpret_cast<const float4*>(ws[dloc]);

    float a0 = 0.f, a1 = 0.f;
#pragma unroll
    for (int q = 0; q < D / 8; q++) {
        const float4 wa = wv[2 * q];
        const float4 wb = wv[2 * q + 1];
        const int base = 8 * q * NN + j;
        a0 += wa.x * Fts[base + 0 * NN] + wa.y * Fts[base + 1 * NN]
            + wa.z * Fts[base + 2 * NN] + wa.w * Fts[base + 3 * NN];
        a1 += wb.x * Fts[base + 4 * NN] + wb.y * Fts[base + 5 * NN]
            + wb.z * Fts[base + 6 * NN] + wb.w * Fts[base + 7 * NN];
    }
    g_tmp[b][m][c0 + dloc][j] = a0 + a1;
}

// ---------------------------------------------------------------------------
// K2: P1/P2[b][i][j] = sum_d Fs[b][d][i] * tmp[b][m][d][j]
//     Mp[b][i][j]    = sum_d Us[b][d][i] * Ut[b][d][j]
//     both[b][e]     = (A_src>0) & (A_tgt>0)
// grid: 16 blocks (one per batch), 256 threads
// ---------------------------------------------------------------------------
__global__ void k2_small(const float* __restrict__ Fs,
                         const float* __restrict__ Us,
                         const float* __restrict__ Ut,
                         const int* __restrict__ As,
                         const int* __restrict__ At) {
    __shared__ float Fss[D * NN];
    __shared__ float t1s[D * NN];
    __shared__ float t2s[D * NN];

    const int b = blockIdx.x;
    const int t = threadIdx.x;

    const float* fs  = Fs + b * D * NN;
    const float* tp1 = &g_tmp[b][0][0][0];
    const float* tp2 = &g_tmp[b][1][0][0];
    for (int idx = t; idx < D * NN; idx += 256) {
        Fss[idx] = fs[idx];
        t1s[idx] = tp1[idx];
        t2s[idx] = tp2[idx];
    }
    __syncthreads();

    const int i = t >> 4;
    const int j = t & 15;

    float p1a = 0.f, p1b = 0.f, p2a = 0.f, p2b = 0.f;
#pragma unroll
    for (int d = 0; d < D; d += 2) {
        const float f0 = Fss[d * NN + i];
        const float f1 = Fss[(d + 1) * NN + i];
        p1a += f0 * t1s[d * NN + j];
        p2a += f0 * t2s[d * NN + j];
        p1b += f1 * t1s[(d + 1) * NN + j];
        p2b += f1 * t2s[(d + 1) * NN + j];
    }
    g_P[b][0][t] = p1a + p1b;
    g_P[b][1][t] = p2a + p2b;

    float mp = 0.f;
#pragma unroll
    for (int d = 0; d < NN; d++)
        mp += Us[b * 256 + d * 16 + i] * Ut[b * 256 + d * 16 + j];
    g_Mp[b][t] = mp;

    if (t < E)
        g_both[b][t] = (As[b * E + t] > 0) && (At[b * E + t] > 0);
}

// ---------------------------------------------------------------------------
// K3: write M[b][p][q], p=i2p*16+i1p, q=i2q*16+i1q
//   M = (p==q ? Mp[p] : 0)
//     + [i2p<i2q][i1p<i1q] both[e2] both[e1]
//       * (P1[i2p,i1p] + P2[i2p,i1q] + P2[i2q,i1p] + P1[i2q,i1q])
//   e(a,b) = a*(29-a)/2 + b - 1  (strict upper triangle, row-major, n=16)
// grid: 256 blocks (b*16 + i2p), 256 threads (q)
// ---------------------------------------------------------------------------
__global__ void k3_write(float* __restrict__ out) {
    __shared__ float P1s[256];
    __shared__ float P2s[256];
    __shared__ float Mps[256];
    __shared__ int   boths[E];

    const int b   = blockIdx.x >> 4;
    const int i2p = blockIdx.x & 15;
    const int t   = threadIdx.x;

    P1s[t] = g_P[b][0][t];
    P2s[t] = g_P[b][1][t];
    Mps[t] = g_Mp[b][t];
    if (t < E) boths[t] = g_both[b][t];
    __syncthreads();

    const int i2q = t >> 4;
    const int i1q = t & 15;

    int e2ok = 0;
    if (i2p < i2q) {
        const int e2 = i2p * (29 - i2p) / 2 + i2q - 1;
        e2ok = boths[e2];
    }

    const float c_p2a = P2s[i2p * 16 + i1q];   // fixed per thread
    const float* p1_row_p = &P1s[i2p * 16];
    const float* p2_col_q = &P2s[i2q * 16];
    const float c_p1b = P1s[i2q * 16 + i1q];

    float* outb = out + b * OUTB + (i2p * 16) * 256 + t;

#pragma unroll
    for (int i1p = 0; i1p < 16; i1p++) {
        const int p = i2p * 16 + i1p;
        float v = (p == t) ? Mps[p] : 0.f;
        if (e2ok && i1p < i1q) {
            const int e1 = i1p * (29 - i1p) / 2 + i1q - 1;
            if (boths[e1])
                v += p1_row_p[i1p] + c_p2a + p2_col_q[i1p] + c_p1b;
        }
        outb[i1p * 256] = v;
    }
}

extern "C" void kernel_launch(void* const* d_in, const int* in_sizes, int n_in,
                              void* d_out, int out_size) {
    const int*   As   = (const int*)d_in[0];
    const int*   At   = (const int*)d_in[1];
    const float* Fs   = (const float*)d_in[2];
    const float* Ft   = (const float*)d_in[3];
    const float* Us   = (const float*)d_in[4];
    const float* Ut   = (const float*)d_in[5];
    const float* lam1 = (const float*)d_in[6];
    const float* lam2 = (const float*)d_in[7];
    float* out = (float*)d_out;

    kW<<<32, 256>>>(lam1, lam2);
    k1_tmp<<<256, 256>>>(Ft);
    k2_small<<<16, 256>>>(Fs, Us, Ut, As, At);
    k3_write<<<256, 256>>>(out);
}

// round 5
// speedup vs baseline: 1.6605x; 1.0743x over previous
#include <cuda_runtime.h>

#define BATCH 16
#define D 128
#define NN 16
#define E 120
#define OUTB (256 * 256)

// Inter-kernel scratch: tmp[b][m][d][j] = relu(lam_m+lam_m^T) @ Ft[b]
__device__ float g_tmp[BATCH][2][D][NN];

// ---------------------------------------------------------------------------
// kA (fused kW+k1): per block (b, m, chunk of 16 W-rows):
//   ws = relu(lam_m[rows] + lam_m^T[rows])  (built in smem, two passes)
//   tmp[b][m][c0+d][j] = sum_d' ws[d][d'] * Ft[b][d'][j]
// grid: 256 = b*16 + m*8 + chunk, 256 threads
// ---------------------------------------------------------------------------
__global__ void kA(const float* __restrict__ Ft,
                   const float* __restrict__ lam1,
                   const float* __restrict__ lam2) {
    __shared__ float Fts[D * NN];     // [d'][j]
    __shared__ float ws[16][132];     // padded rows: no float4 bank conflict

    const int b  = blockIdx.x >> 4;
    const int m  = (blockIdx.x >> 3) & 1;
    const int c0 = (blockIdx.x & 7) * 16;
    const int t  = threadIdx.x;

    const float* lam = m ? lam2 : lam1;
    const float* ft  = Ft + b * D * NN;

    for (int idx = t; idx < D * NN; idx += 256) Fts[idx] = ft[idx];

    // pass 1: direct rows, coalesced (consecutive t -> consecutive dp)
    for (int idx = t; idx < 16 * D; idx += 256) {
        const int d  = idx >> 7;
        const int dp = idx & 127;
        ws[d][dp] = lam[(c0 + d) * D + dp];
    }
    __syncthreads();

    // pass 2: transposed term + relu. Mapping d=idx&15 keeps each warp-load
    // on two contiguous 64B runs of lam (vs 32 scattered sectors).
    for (int idx = t; idx < 16 * D; idx += 256) {
        const int d  = idx & 15;
        const int dp = idx >> 4;
        const float v = ws[d][dp] + lam[dp * D + c0 + d];
        ws[d][dp] = v > 0.f ? v : 0.f;
    }
    __syncthreads();

    const int j    = t & 15;
    const int dloc = t >> 4;
    const float4* wv = reinterpret_cast<const float4*>(ws[dloc]);

    float a0 = 0.f, a1 = 0.f;
#pragma unroll
    for (int q = 0; q < D / 8; q++) {
        const float4 wa = wv[2 * q];
        const float4 wb = wv[2 * q + 1];
        const int base = 8 * q * NN + j;
        a0 += wa.x * Fts[base + 0 * NN] + wa.y * Fts[base + 1 * NN]
            + wa.z * Fts[base + 2 * NN] + wa.w * Fts[base + 3 * NN];
        a1 += wb.x * Fts[base + 4 * NN] + wb.y * Fts[base + 5 * NN]
            + wb.z * Fts[base + 6 * NN] + wb.w * Fts[base + 7 * NN];
    }
    g_tmp[b][m][c0 + dloc][j] = a0 + a1;
}

// ---------------------------------------------------------------------------
// kB (fused k2+k3): per block (b, i2p):
//   P1/P2[i][j] = sum_d Fs[d][i] * tmp[m][d][j]   (redundant x16, parallel)
//   mp[j]       = sum_d Us[d][i2p] * Ut[d][j]     (only needed Mp row)
//   both[e]     = (A_src>0)&(A_tgt>0)
//   then write 16x256 output rows with float4 coalesced stores.
// grid: 256 = b*16 + i2p, 256 threads
// ---------------------------------------------------------------------------
__global__ void kB(const float* __restrict__ Fs,
                   const float* __restrict__ Us,
                   const float* __restrict__ Ut,
                   const int* __restrict__ As,
                   const int* __restrict__ At,
                   float* __restrict__ out) {
    __shared__ float FsT[16 * 132];   // [i][d], padded
    __shared__ float T1[16 * 132];    // [j][d]
    __shared__ float T2[16 * 132];    // [j][d]
    __shared__ float P1s[256];
    __shared__ float P2s[256];
    __shared__ float mps[16];
    __shared__ int   boths[E];

    const int b   = blockIdx.x >> 4;
    const int i2p = blockIdx.x & 15;
    const int t   = threadIdx.x;

    const float* fs  = Fs + b * D * NN;
    const float* tp1 = &g_tmp[b][0][0][0];
    const float* tp2 = &g_tmp[b][1][0][0];

    // load + transpose into [minor][d] layout for float4 reduction reads
    for (int idx = t; idx < D * NN; idx += 256) {
        const int w = (idx & 15) * 132 + (idx >> 4);
        FsT[w] = fs[idx];
        T1[w]  = tp1[idx];
        T2[w]  = tp2[idx];
    }

    if (t < E)
        boths[t] = (As[b * E + t] > 0) && (At[b * E + t] > 0);

    if (t < 16) {
        float mp = 0.f;
#pragma unroll
        for (int d = 0; d < NN; d++)
            mp += Us[b * 256 + d * 16 + i2p] * Ut[b * 256 + d * 16 + t];
        mps[t] = mp;
    }
    __syncthreads();

    // P1/P2: thread (i = t>>4, j = t&15), 128-deep dot via float4 LDS
    {
        const int i = t >> 4;
        const int j = t & 15;
        const float4* fv  = reinterpret_cast<const float4*>(&FsT[i * 132]);
        const float4* t1v = reinterpret_cast<const float4*>(&T1[j * 132]);
        const float4* t2v = reinterpret_cast<const float4*>(&T2[j * 132]);

        float p1a = 0.f, p1b = 0.f, p2a = 0.f, p2b = 0.f;
#pragma unroll
        for (int q = 0; q < D / 4; q++) {
            const float4 f  = fv[q];
            const float4 x1 = t1v[q];
            const float4 x2 = t2v[q];
            p1a += f.x * x1.x + f.y * x1.y;
            p1b += f.z * x1.z + f.w * x1.w;
            p2a += f.x * x2.x + f.y * x2.y;
            p2b += f.z * x2.z + f.w * x2.w;
        }
        P1s[t] = p1a + p1b;
        P2s[t] = p2a + p2b;
    }
    __syncthreads();

    // Write phase. thread: i1p = t>>4, tq = t&15.
    // store s (0..3): q0 = s*64 + tq*4 -> warp writes 2 contiguous 256B runs.
    const int i1p = t >> 4;
    const int tq  = t & 15;
    const int p   = i2p * 16 + i1p;

    const float a_p1   = P1s[p];                    // P1[i2p,i1p]
    const int   ebase1 = i1p * (29 - i1p) / 2 - 1;  // e1 = ebase1 + i1q
    const float* p1_prow = &P1s[i2p * 16];          // P2s uses same indexing
    (void)p1_prow;

    float* orow = out + b * OUTB + p * 256;

#pragma unroll
    for (int s = 0; s < 4; s++) {
        const int q0  = s * 64 + tq * 4;
        const int i2q = q0 >> 4;
        const int i1q0 = q0 & 15;

        int e2ok = 0;
        if (i2p < i2q) {
            const int e2 = i2p * (29 - i2p) / 2 + i2q - 1;
            e2ok = boths[e2];
        }
        const float c_p2 = P2s[i2q * 16 + i1p];     // P2[i2q,i1p]

        float4 v;
        float* vp = &v.x;
#pragma unroll
        for (int k = 0; k < 4; k++) {
            const int i1q = i1q0 + k;
            float val = (i2q == i2p && i1q == i1p) ? mps[i1p] : 0.f;
            if (e2ok && i1p < i1q && boths[ebase1 + i1q])
                val += a_p1 + P2s[i2p * 16 + i1q] + c_p2 + P1s[i2q * 16 + i1q];
            vp[k] = val;
        }
        *reinterpret_cast<float4*>(orow + q0) = v;
    }
}

extern "C" void kernel_launch(void* const* d_in, const int* in_sizes, int n_in,
                              void* d_out, int out_size) {
    const int*   As   = (const int*)d_in[0];
    const int*   At   = (const int*)d_in[1];
    const float* Fs   = (const float*)d_in[2];
    const float* Ft   = (const float*)d_in[3];
    const float* Us   = (const float*)d_in[4];
    const float* Ut   = (const float*)d_in[5];
    const float* lam1 = (const float*)d_in[6];
    const float* lam2 = (const float*)d_in[7];
    float* out = (float*)d_out;

    kA<<<256, 256>>>(Ft, lam1, lam2);
    kB<<<256, 256>>>(Fs, Us, Ut, As, At, out);
}